// round 1
// baseline (speedup 1.0000x reference)
#include <cuda_runtime.h>
#include <cstdint>

#define K 128
#define D 128
#define TPB 256

// Scratch (allocation-free rule: __device__ globals)
__device__ float g_centroid[K * D];
__device__ float g_c2[K];
__device__ float g_acc[K];
__device__ float g_masksum;

// ---- packed f32x2 helpers (sm_100+) ----
__device__ __forceinline__ unsigned long long ffma2(unsigned long long a,
                                                    unsigned long long b,
                                                    unsigned long long c) {
    unsigned long long d_;
    asm("fma.rn.f32x2 %0, %1, %2, %3;" : "=l"(d_) : "l"(a), "l"(b), "l"(c));
    return d_;
}
__device__ __forceinline__ unsigned long long pack2(float lo, float hi) {
    unsigned long long r;
    asm("mov.b64 %0, {%1, %2};" : "=l"(r) : "f"(lo), "f"(hi));
    return r;
}
__device__ __forceinline__ float2 unpack2(unsigned long long v) {
    float lo, hi;
    asm("mov.b64 {%0, %1}, %2;" : "=f"(lo), "=f"(hi) : "l"(v));
    return make_float2(lo, hi);
}

// ---- Kernel 1: exp-map centroids onto Poincare ball, compute c2, zero accumulators ----
__global__ void prep_kernel(const float* __restrict__ cw) {
    int k = threadIdx.x;
    if (k >= K) return;
    g_acc[k] = 0.0f;
    if (k == 0) g_masksum = 0.0f;

    const float* row = cw + k * D;
    float ss = 0.0f;
#pragma unroll 4
    for (int d = 0; d < D; d++) ss += row[d] * row[d];
    float norm = sqrtf(ss);
    norm = fmaxf(norm, 1e-5f);                 // clip(norm, EPS, None)
    float t = tanhf(fminf(norm, 15.0f));       // tanh(clip(norm, None, 15))
    float s = t / norm;
    float c2 = 0.0f;
#pragma unroll 4
    for (int d = 0; d < D; d++) {
        float o = row[d] * s;
        g_centroid[k * D + d] = o;
        c2 += o * o;
    }
    g_c2[k] = c2;
}

// ---- Kernel 2: pairwise Poincare distance + column (per-k) partial sums ----
__global__ void __launch_bounds__(TPB, 1)
dist_kernel(const float* __restrict__ x,
            const float* __restrict__ mask,
            float* __restrict__ out_node,   // [N, K]
            int N) {
    extern __shared__ float smem[];
    float* sc   = smem;              // K*D centroid tile
    float* sc2  = smem + K * D;      // K
    float* sacc = sc2 + K;           // K per-block column sums

    // stage centroids into smem
    {
        const float4* g4 = (const float4*)g_centroid;
        float4* s4 = (float4*)sc;
        for (int i = threadIdx.x; i < (K * D) / 4; i += TPB) s4[i] = g4[i];
        if (threadIdx.x < K) {
            sc2[threadIdx.x] = g_c2[threadIdx.x];
            sacc[threadIdx.x] = 0.0f;
        }
    }
    __syncthreads();

    const int n = blockIdx.x * TPB + threadIdx.x;
    const bool valid = (n < N);
    const int lane = threadIdx.x & 31;
    const float m = valid ? mask[n] : 0.0f;

    // mask sum contribution (once per warp)
    {
        float wm = m;
#pragma unroll
        for (int off = 16; off; off >>= 1) wm += __shfl_xor_sync(0xffffffffu, wm, off);
        if (lane == 0) atomicAdd(&g_masksum, wm);
    }

    // load this node's row into registers (clamped row for tail threads; m=0 kills contribution)
    const int nn = valid ? n : (N - 1);
    unsigned long long xr[D / 2];
    float x2 = 0.0f;
    {
        const float4* xrow = (const float4*)(x + (size_t)nn * D);
#pragma unroll
        for (int i = 0; i < D / 4; i++) {
            float4 v = xrow[i];
            xr[2 * i]     = pack2(v.x, v.y);
            xr[2 * i + 1] = pack2(v.z, v.w);
            x2 = fmaf(v.x, v.x, x2);
            x2 = fmaf(v.y, v.y, x2);
            x2 = fmaf(v.z, v.z, x2);
            x2 = fmaf(v.w, v.w, x2);
        }
    }
    const float omx2 = 1.0f - x2;
    float* orow = out_node + (size_t)n * K;

#pragma unroll 1
    for (int kb = 0; kb < K; kb += 4) {
        float vout[4];
#pragma unroll
        for (int u = 0; u < 4; u++) {
            const int k = kb + u;
            const ulonglong2* crow = (const ulonglong2*)(sc + k * D);
            unsigned long long a0 = 0ull, a1 = 0ull, a2 = 0ull, a3 = 0ull;
#pragma unroll
            for (int d = 0; d < 16; d++) {
                ulonglong2 c0 = crow[d];
                ulonglong2 c1 = crow[d + 16];
                a0 = ffma2(xr[2 * d],      c0.x, a0);
                a1 = ffma2(xr[2 * d + 1],  c0.y, a1);
                a2 = ffma2(xr[32 + 2 * d], c1.x, a2);
                a3 = ffma2(xr[33 + 2 * d], c1.y, a3);
            }
            float2 f0 = unpack2(a0), f1 = unpack2(a1), f2 = unpack2(a2), f3 = unpack2(a3);
            float dot = ((f0.x + f0.y) + (f1.x + f1.y)) + ((f2.x + f2.y) + (f3.x + f3.y));

            const float c2k = sc2[k];
            float sq    = fmaxf(x2 + c2k - 2.0f * dot, 0.0f);
            float denom = fmaxf(omx2 * (1.0f - c2k), 1e-5f);
            float arg   = fmaxf(1.0f + 2.0f * sq / denom, 1.0f + 1e-7f);
            float dist  = acoshf(arg);
            float val   = dist * m;
            vout[u] = val;

            // warp reduction across 32 nodes for column k
            float w = val;
#pragma unroll
            for (int off = 16; off; off >>= 1) w += __shfl_xor_sync(0xffffffffu, w, off);
            if (lane == 0) atomicAdd(&sacc[k], w);
        }
        if (valid)
            *(float4*)(orow + kb) = make_float4(vout[0], vout[1], vout[2], vout[3]);
    }

    __syncthreads();
    if (threadIdx.x < K)
        atomicAdd(&g_acc[threadIdx.x], sacc[threadIdx.x]);
}

// ---- Kernel 3: graph_centroid_dist = colsum / masksum ----
__global__ void finish_kernel(float* __restrict__ out_graph) {
    int k = threadIdx.x;
    if (k < K) out_graph[k] = g_acc[k] / g_masksum;
}

extern "C" void kernel_launch(void* const* d_in, const int* in_sizes, int n_in,
                              void* d_out, int out_size) {
    const float* x    = (const float*)d_in[0];  // node_repr [N, D]
    const float* mask = (const float*)d_in[1];  // mask [N, 1]
    const float* cw   = (const float*)d_in[2];  // centroid_weight [K, D]
    const int N = in_sizes[1];                  // mask element count = N
    float* out = (float*)d_out;                 // [K graph][N*K node]

    const int smem_bytes = (K * D + 2 * K) * (int)sizeof(float);
    cudaFuncSetAttribute(dist_kernel, cudaFuncAttributeMaxDynamicSharedMemorySize, smem_bytes);

    prep_kernel<<<1, K>>>(cw);
    const int blocks = (N + TPB - 1) / TPB;
    dist_kernel<<<blocks, TPB, smem_bytes>>>(x, mask, out + K, N);
    finish_kernel<<<1, K>>>(out);
}

// round 5
// speedup vs baseline: 8.4699x; 8.4699x over previous
#include <cuda_runtime.h>
#include <cuda_bf16.h>
#include <cstdint>

#define KC 128   // centroids
#define DD 128   // dims
#define TM 128   // nodes per CTA tile
#define TPB 256

// ---- device scratch (allocation-free rule) ----
__device__ __nv_bfloat16 g_cent[KC * DD];
__device__ float g_c2[KC];
__device__ float g_acc[KC];
__device__ float g_masksum;

// ---- smem layout (bytes) ----
#define SM_A    0                    // 32 KB: X tile bf16 [128 rows][128], swizzled
#define SM_B    32768                // 32 KB: C tile bf16 [128 rows][128], swizzled
#define SM_X2   65536                // 512 B
#define SM_MS   66048                // 512 B
#define SM_C2   66560                // 512 B
#define SM_SCOL 67072                // 512 B
#define SM_TOTAL 67584               // -> 2 CTAs/SM

__device__ __forceinline__ uint32_t smem_u32(const void* p) {
    uint32_t a;
    asm("{ .reg .u64 t; cvta.to.shared.u64 t, %1; cvt.u32.u64 %0, t; }" : "=r"(a) : "l"(p));
    return a;
}
__device__ __forceinline__ uint32_t bf2u(__nv_bfloat162 h) {
    return *reinterpret_cast<uint32_t*>(&h);
}
__device__ __forceinline__ void ldsm4(uint32_t& r0, uint32_t& r1, uint32_t& r2, uint32_t& r3,
                                      uint32_t addr) {
    asm volatile("ldmatrix.sync.aligned.m8n8.x4.shared.b16 {%0,%1,%2,%3}, [%4];"
                 : "=r"(r0), "=r"(r1), "=r"(r2), "=r"(r3) : "r"(addr));
}
__device__ __forceinline__ void mma16816(float* c, const uint32_t* a, const uint32_t* b) {
    asm volatile(
        "mma.sync.aligned.m16n8k16.row.col.f32.bf16.bf16.f32 "
        "{%0,%1,%2,%3}, {%4,%5,%6,%7}, {%8,%9}, {%0,%1,%2,%3};"
        : "+f"(c[0]), "+f"(c[1]), "+f"(c[2]), "+f"(c[3])
        : "r"(a[0]), "r"(a[1]), "r"(a[2]), "r"(a[3]), "r"(b[0]), "r"(b[1]));
}
__device__ __forceinline__ float pdist(float dot, float x2, float omx2, float c2) {
    float sq  = fmaxf(x2 + c2 - 2.0f * dot, 0.0f);
    float den = fmaxf(omx2 * (1.0f - c2), 1e-5f);
    float arg = fmaxf(fmaf(2.0f, __fdividef(sq, den), 1.0f), 1.0f + 1e-7f);
    return __logf(arg + __fsqrt_rn(fmaf(arg, arg, -1.0f)));
}

// ---- Kernel 1: exp-map centroids -> bf16, exact fp32 c2, zero accumulators ----
__global__ void prep_kernel(const float* __restrict__ cw) {
    int wid = threadIdx.x >> 5, lid = threadIdx.x & 31;
    int k = blockIdx.x * 4 + wid;            // 32 blocks x 4 warps -> k 0..127
    if (blockIdx.x == 0) {
        if (threadIdx.x < KC) g_acc[threadIdx.x] = 0.0f;
        if (threadIdx.x == 0) g_masksum = 0.0f;
    }
    float4 v = ((const float4*)(cw + (size_t)k * DD))[lid];
    float ss = v.x * v.x + v.y * v.y + v.z * v.z + v.w * v.w;
#pragma unroll
    for (int o = 16; o; o >>= 1) ss += __shfl_xor_sync(0xffffffffu, ss, o);
    float norm = fmaxf(sqrtf(ss), 1e-5f);
    float s = tanhf(fminf(norm, 15.0f)) / norm;
    float4 o4 = make_float4(v.x * s, v.y * s, v.z * s, v.w * s);
    float c2 = o4.x * o4.x + o4.y * o4.y + o4.z * o4.z + o4.w * o4.w;
#pragma unroll
    for (int o = 16; o; o >>= 1) c2 += __shfl_xor_sync(0xffffffffu, c2, o);
    if (lid == 0) g_c2[k] = c2;
    __nv_bfloat16* dst = g_cent + (size_t)k * DD + lid * 4;
    dst[0] = __float2bfloat16(o4.x);
    dst[1] = __float2bfloat16(o4.y);
    dst[2] = __float2bfloat16(o4.z);
    dst[3] = __float2bfloat16(o4.w);
}

// ---- Kernel 2: HMMA (mma.sync bf16) GEMM + Poincare epilogue ----
__global__ void __launch_bounds__(TPB, 2)
dist_kernel(const float* __restrict__ x,
            const float* __restrict__ mask,
            float* __restrict__ out_node, int N) {
    extern __shared__ char smem[];
    const uint32_t sb = smem_u32(smem);
    const int tid = threadIdx.x, wid = tid >> 5, l = tid & 31;
    const int wr = wid & 3, wc = wid >> 2;   // warp grid 4 (rows) x 2 (cols)

    float* x2s  = (float*)(smem + SM_X2);
    float* ms   = (float*)(smem + SM_MS);
    float* c2s  = (float*)(smem + SM_C2);
    float* scol = (float*)(smem + SM_SCOL);

    const int tile0 = blockIdx.x * TM;

    if (tid < KC) {
        c2s[tid] = g_c2[tid];
        scol[tid] = 0.0f;
        int gr = tile0 + tid;
        ms[tid] = (gr < N) ? mask[gr] : 0.0f;
    }

    // ---- stage X tile (fp32 -> bf16) + exact x2 ----
#pragma unroll
    for (int j = 0; j < 8; j++) {
        int i = tid + TPB * j;               // chunk index: 2048 chunks of 16B
        int row = i >> 4, c = i & 15;
        int gr = tile0 + row; if (gr >= N) gr = N - 1;
        const float4* xp = (const float4*)x + (size_t)gr * 32 + c * 2;
        float4 v0 = xp[0], v1 = xp[1];
        float ss = v0.x * v0.x + v0.y * v0.y + v0.z * v0.z + v0.w * v0.w
                 + v1.x * v1.x + v1.y * v1.y + v1.z * v1.z + v1.w * v1.w;
#pragma unroll
        for (int o = 8; o; o >>= 1) ss += __shfl_xor_sync(0xffffffffu, ss, o);
        if ((l & 15) == 0) x2s[row] = ss;
        uint4 st;
        st.x = bf2u(__float22bfloat162_rn(make_float2(v0.x, v0.y)));
        st.y = bf2u(__float22bfloat162_rn(make_float2(v0.z, v0.w)));
        st.z = bf2u(__float22bfloat162_rn(make_float2(v1.x, v1.y)));
        st.w = bf2u(__float22bfloat162_rn(make_float2(v1.z, v1.w)));
        *(uint4*)(smem + SM_A + row * 256 + ((c ^ (row & 7)) << 4)) = st;
    }
    // ---- stage C tile (prepped bf16) ----
#pragma unroll
    for (int j = 0; j < 8; j++) {
        int i = tid + TPB * j;
        int row = i >> 4, c = i & 15;
        uint4 v = ((const uint4*)g_cent)[i];
        *(uint4*)(smem + SM_B + row * 256 + ((c ^ (row & 7)) << 4)) = v;
    }
    __syncthreads();

    // masksum (one warp)
    if (wid == 0) {
        float wm = ms[l] + ms[l + 32] + ms[l + 64] + ms[l + 96];
#pragma unroll
        for (int o = 16; o; o >>= 1) wm += __shfl_xor_sync(0xffffffffu, wm, o);
        if (l == 0) atomicAdd(&g_masksum, wm);
    }

    // ---- mainloop: warp tile 32 (rows) x 64 (cols), 8 k-steps ----
    float acc[2][8][4];
#pragma unroll
    for (int mi = 0; mi < 2; mi++)
#pragma unroll
        for (int t = 0; t < 8; t++)
#pragma unroll
            for (int u = 0; u < 4; u++) acc[mi][t][u] = 0.0f;

    const int a_row0 = wr * 32 + (l & 15);   // + mi*16
    const int a_hi   = l >> 4;
    const int b_row0 = wc * 64 + ((l >> 4) << 3) + (l & 7);  // + bt2*16
    const int b_hi   = (l >> 3) & 1;

#pragma unroll
    for (int kk = 0; kk < 8; kk++) {
        uint32_t af[2][4];
#pragma unroll
        for (int mi = 0; mi < 2; mi++) {
            int row = a_row0 + mi * 16;
            uint32_t ad = sb + SM_A + row * 256 + ((((kk << 1) | a_hi) ^ (row & 7)) << 4);
            ldsm4(af[mi][0], af[mi][1], af[mi][2], af[mi][3], ad);
        }
        uint32_t bf[8][2];
#pragma unroll
        for (int bt2 = 0; bt2 < 4; bt2++) {
            int nrow = b_row0 + bt2 * 16;
            uint32_t bd = sb + SM_B + nrow * 256 + ((((kk << 1) | b_hi) ^ (nrow & 7)) << 4);
            uint32_t r0, r1, r2, r3;
            ldsm4(r0, r1, r2, r3, bd);
            bf[bt2 * 2][0] = r0; bf[bt2 * 2][1] = r1;
            bf[bt2 * 2 + 1][0] = r2; bf[bt2 * 2 + 1][1] = r3;
        }
#pragma unroll
        for (int mi = 0; mi < 2; mi++)
#pragma unroll
            for (int t = 0; t < 8; t++) mma16816(acc[mi][t], af[mi], bf[t]);
    }

    // ---- epilogue ----
#pragma unroll
    for (int mi = 0; mi < 2; mi++) {
        int r0 = wr * 32 + mi * 16 + (l >> 2);
        int r1 = r0 + 8;
        float m0 = ms[r0], m1 = ms[r1];
        float x20 = x2s[r0], x21 = x2s[r1];
        float o0 = 1.0f - x20, o1 = 1.0f - x21;
        bool v0ok = (tile0 + r0) < N, v1ok = (tile0 + r1) < N;
        float* p0r = out_node + (size_t)(tile0 + r0) * KC;
        float* p1r = out_node + (size_t)(tile0 + r1) * KC;
#pragma unroll
        for (int t = 0; t < 8; t++) {
            int col = wc * 64 + t * 8 + ((l & 3) << 1);
            float2 c2p = *(float2*)(c2s + col);
            float d0 = pdist(acc[mi][t][0], x20, o0, c2p.x) * m0;
            float d1 = pdist(acc[mi][t][1], x20, o0, c2p.y) * m0;
            float d2 = pdist(acc[mi][t][2], x21, o1, c2p.x) * m1;
            float d3 = pdist(acc[mi][t][3], x21, o1, c2p.y) * m1;
            if (v0ok) *(float2*)(p0r + col) = make_float2(d0, d1);
            if (v1ok) *(float2*)(p1r + col) = make_float2(d2, d3);
            float s0 = d0 + d2, s1 = d1 + d3;
#pragma unroll
            for (int o = 4; o <= 16; o <<= 1) {
                s0 += __shfl_xor_sync(0xffffffffu, s0, o);
                s1 += __shfl_xor_sync(0xffffffffu, s1, o);
            }
            if ((l >> 2) == 0) {
                atomicAdd(&scol[col], s0);
                atomicAdd(&scol[col + 1], s1);
            }
        }
    }

    __syncthreads();
    if (tid < KC) atomicAdd(&g_acc[tid], scol[tid]);
}

// ---- Kernel 3 ----
__global__ void finish_kernel(float* __restrict__ out_graph) {
    int k = threadIdx.x;
    if (k < KC) out_graph[k] = g_acc[k] / g_masksum;
}

extern "C" void kernel_launch(void* const* d_in, const int* in_sizes, int n_in,
                              void* d_out, int out_size) {
    const float* x    = (const float*)d_in[0];
    const float* mask = (const float*)d_in[1];
    const float* cw   = (const float*)d_in[2];
    const int N = in_sizes[1];
    float* out = (float*)d_out;

    cudaFuncSetAttribute(dist_kernel, cudaFuncAttributeMaxDynamicSharedMemorySize, SM_TOTAL);

    prep_kernel<<<32, 128>>>(cw);
    const int blocks = (N + TM - 1) / TM;
    dist_kernel<<<blocks, TPB, SM_TOTAL>>>(x, mask, out + KC, N);
    finish_kernel<<<1, KC>>>(out);
}

// round 6
// speedup vs baseline: 8.6187x; 1.0176x over previous
#include <cuda_runtime.h>
#include <cuda_bf16.h>
#include <cstdint>

#define KC 128   // centroids
#define DD 128   // dims
#define TM 128   // nodes per tile
#define TPB 512  // 16 warps, 4x4 warp grid

// ---- device scratch ----
__device__ __nv_bfloat16 g_cent[KC * DD];
__device__ float g_c2[KC];
__device__ float g_acc[KC];
__device__ float g_masksum;

// ---- smem layout (bytes) ----
#define XF_STRIDE 576                 // 512B row + 64B pad (conflict-free LDS.128)
#define SM_XF0  0                     // 73728: fp32 X tile buf 0
#define SM_XF1  73728                 // 73728: fp32 X tile buf 1
#define SM_A    147456                // 32768: X bf16, swizzled
#define SM_B    180224                // 32768: C bf16, swizzled
#define SM_X2   212992                // 512
#define SM_MS   213504                // 512
#define SM_C2   214016                // 512
#define SM_SCOL 214528                // 512
#define SM_MSUM 215040                // 4
#define SM_TOTAL 215072

__device__ __forceinline__ uint32_t smem_u32(const void* p) {
    uint32_t a;
    asm("{ .reg .u64 t; cvta.to.shared.u64 t, %1; cvt.u32.u64 %0, t; }" : "=r"(a) : "l"(p));
    return a;
}
__device__ __forceinline__ uint32_t bf2u(__nv_bfloat162 h) {
    return *reinterpret_cast<uint32_t*>(&h);
}
__device__ __forceinline__ void ldsm4(uint32_t& r0, uint32_t& r1, uint32_t& r2, uint32_t& r3,
                                      uint32_t addr) {
    asm volatile("ldmatrix.sync.aligned.m8n8.x4.shared.b16 {%0,%1,%2,%3}, [%4];"
                 : "=r"(r0), "=r"(r1), "=r"(r2), "=r"(r3) : "r"(addr));
}
__device__ __forceinline__ void mma16816(float* c, const uint32_t* a, const uint32_t* b) {
    asm volatile(
        "mma.sync.aligned.m16n8k16.row.col.f32.bf16.bf16.f32 "
        "{%0,%1,%2,%3}, {%4,%5,%6,%7}, {%8,%9}, {%0,%1,%2,%3};"
        : "+f"(c[0]), "+f"(c[1]), "+f"(c[2]), "+f"(c[3])
        : "r"(a[0]), "r"(a[1]), "r"(a[2]), "r"(a[3]), "r"(b[0]), "r"(b[1]));
}
__device__ __forceinline__ float sqrt_approx(float v) {
    float r; asm("sqrt.approx.f32 %0, %1;" : "=f"(r) : "f"(v)); return r;
}
__device__ __forceinline__ float pdist(float dot, float x2, float omx2, float c2) {
    float sq  = fmaxf(x2 + c2 - 2.0f * dot, 0.0f);
    float den = fmaxf(omx2 * (1.0f - c2), 1e-5f);
    float arg = fmaxf(fmaf(2.0f, __fdividef(sq, den), 1.0f), 1.0f + 1e-7f);
    return __logf(arg + sqrt_approx(fmaf(arg, arg, -1.0f)));
}
// issue async copy of one fp32 X tile (64KB) into xf buffer
__device__ __forceinline__ void stage_async(uint32_t xf, const float* __restrict__ x,
                                            int tile0, int N, int tid) {
#pragma unroll
    for (int j = 0; j < 8; j++) {
        int i = tid + TPB * j;         // 4096 chunks of 16B
        int row = i >> 5, c = i & 31;
        int gr = tile0 + row; if (gr >= N) gr = N - 1;
        const float* src = x + (size_t)gr * DD + c * 4;
        uint32_t dst = xf + row * XF_STRIDE + c * 16;
        asm volatile("cp.async.cg.shared.global [%0], [%1], 16;" :: "r"(dst), "l"(src));
    }
    asm volatile("cp.async.commit_group;" ::: "memory");
}

// ---- Kernel 1: exp-map centroids -> bf16, exact fp32 c2, zero accumulators ----
__global__ void prep_kernel(const float* __restrict__ cw) {
    int wid = threadIdx.x >> 5, lid = threadIdx.x & 31;
    int k = blockIdx.x * 4 + wid;
    if (blockIdx.x == 0) {
        if (threadIdx.x < KC) g_acc[threadIdx.x] = 0.0f;
        if (threadIdx.x == 0) g_masksum = 0.0f;
    }
    float4 v = ((const float4*)(cw + (size_t)k * DD))[lid];
    float ss = v.x * v.x + v.y * v.y + v.z * v.z + v.w * v.w;
#pragma unroll
    for (int o = 16; o; o >>= 1) ss += __shfl_xor_sync(0xffffffffu, ss, o);
    float norm = fmaxf(sqrtf(ss), 1e-5f);
    float s = tanhf(fminf(norm, 15.0f)) / norm;
    float4 o4 = make_float4(v.x * s, v.y * s, v.z * s, v.w * s);
    float c2 = o4.x * o4.x + o4.y * o4.y + o4.z * o4.z + o4.w * o4.w;
#pragma unroll
    for (int o = 16; o; o >>= 1) c2 += __shfl_xor_sync(0xffffffffu, c2, o);
    if (lid == 0) g_c2[k] = c2;
    __nv_bfloat16* dst = g_cent + (size_t)k * DD + lid * 4;
    dst[0] = __float2bfloat16(o4.x);
    dst[1] = __float2bfloat16(o4.y);
    dst[2] = __float2bfloat16(o4.z);
    dst[3] = __float2bfloat16(o4.w);
}

// ---- Kernel 2: persistent HMMA GEMM + Poincare epilogue, cp.async pipelined ----
__global__ void __launch_bounds__(TPB, 1)
dist_kernel(const float* __restrict__ x,
            const float* __restrict__ mask,
            float* __restrict__ out_node, int N, int ntiles) {
    extern __shared__ char smem[];
    const uint32_t sb = smem_u32(smem);
    const int tid = threadIdx.x, wid = tid >> 5, l = tid & 31;
    const int wr = wid & 3, wc = wid >> 2;     // 4x4 warp grid: 32-row x 32-col warp tile

    float* x2s  = (float*)(smem + SM_X2);
    float* ms   = (float*)(smem + SM_MS);
    float* c2s  = (float*)(smem + SM_C2);
    float* scol = (float*)(smem + SM_SCOL);
    float* msum = (float*)(smem + SM_MSUM);

    // stage B (centroids) ONCE, swizzled for ldmatrix
#pragma unroll
    for (int j = 0; j < 4; j++) {
        int i = tid + TPB * j;                 // 2048 chunks of 16B
        int row = i >> 4, c = i & 15;
        uint4 v = ((const uint4*)g_cent)[i];
        *(uint4*)(smem + SM_B + row * 256 + ((c ^ (row & 7)) << 4)) = v;
    }
    if (tid < KC) { c2s[tid] = g_c2[tid]; scol[tid] = 0.0f; }
    if (tid == 0) *msum = 0.0f;

    // prologue: prefetch first tile
    int tile = blockIdx.x;
    if (tile < ntiles) stage_async(sb + SM_XF0, x, tile * TM, N, tid);
    int p = 0;

    const int a_row0 = wr * 32 + (l & 15);
    const int a_hi   = l >> 4;
    const int b_row0 = wc * 32 + ((l >> 4) << 3) + (l & 7);
    const int b_hi   = (l >> 3) & 1;
    const int cvrow  = wid * 8 + (l >> 2);     // convert-phase row for this thread

    for (; tile < ntiles; tile += gridDim.x, p ^= 1) {
        const int tile0 = tile * TM;
        const uint32_t xf = (p == 0) ? SM_XF0 : SM_XF1;

        asm volatile("cp.async.wait_group 0;" ::: "memory");
        __syncthreads();                       // XF[p] complete, A free

        // convert: fp32 smem -> exact x2 + bf16 A tile (swizzled); load mask
        {
            int gr = tile0 + cvrow;
            if ((l & 3) == 0) ms[cvrow] = (gr < N) ? mask[gr] : 0.0f;
            float ss = 0.0f;
            const char* base = smem + xf + cvrow * XF_STRIDE;
            char* abase = smem + SM_A + cvrow * 256;
            int swr = cvrow & 7;
#pragma unroll
            for (int t = 0; t < 8; t++) {
                int c4 = (l & 3) + 4 * t;
                float4 v = *(const float4*)(base + c4 * 16);
                ss += v.x * v.x + v.y * v.y + v.z * v.z + v.w * v.w;
                uint2 st;
                st.x = bf2u(__float22bfloat162_rn(make_float2(v.x, v.y)));
                st.y = bf2u(__float22bfloat162_rn(make_float2(v.z, v.w)));
                *(uint2*)(abase + ((((c4 >> 1) ^ swr) << 4) | ((c4 & 1) << 3))) = st;
            }
            ss += __shfl_xor_sync(0xffffffffu, ss, 1);
            ss += __shfl_xor_sync(0xffffffffu, ss, 2);
            if ((l & 3) == 0) x2s[cvrow] = ss;
        }

        // prefetch next tile (overlaps MMA + epilogue)
        int nxt = tile + gridDim.x;
        if (nxt < ntiles) stage_async(sb + ((p == 0) ? SM_XF1 : SM_XF0), x, nxt * TM, N, tid);

        __syncthreads();                       // A, x2s, ms ready

        // masksum for this tile (warp 0)
        if (wid == 0) {
            float wm = ms[l] + ms[l + 32] + ms[l + 64] + ms[l + 96];
#pragma unroll
            for (int o = 16; o; o >>= 1) wm += __shfl_xor_sync(0xffffffffu, wm, o);
            if (l == 0) *msum += wm;
        }

        // mainloop: warp tile 32x32, 8 k-steps
        float acc[2][4][4];
#pragma unroll
        for (int mi = 0; mi < 2; mi++)
#pragma unroll
            for (int t = 0; t < 4; t++)
#pragma unroll
                for (int u = 0; u < 4; u++) acc[mi][t][u] = 0.0f;

#pragma unroll
        for (int kk = 0; kk < 8; kk++) {
            uint32_t af[2][4];
#pragma unroll
            for (int mi = 0; mi < 2; mi++) {
                int row = a_row0 + mi * 16;
                uint32_t ad = sb + SM_A + row * 256 + ((((kk << 1) | a_hi) ^ (row & 7)) << 4);
                ldsm4(af[mi][0], af[mi][1], af[mi][2], af[mi][3], ad);
            }
            uint32_t bf[4][2];
#pragma unroll
            for (int nt2 = 0; nt2 < 2; nt2++) {
                int nrow = b_row0 + nt2 * 16;
                uint32_t bd = sb + SM_B + nrow * 256 + ((((kk << 1) | b_hi) ^ (nrow & 7)) << 4);
                uint32_t r0, r1, r2, r3;
                ldsm4(r0, r1, r2, r3, bd);
                bf[nt2 * 2][0] = r0;     bf[nt2 * 2][1] = r1;
                bf[nt2 * 2 + 1][0] = r2; bf[nt2 * 2 + 1][1] = r3;
            }
#pragma unroll
            for (int mi = 0; mi < 2; mi++)
#pragma unroll
                for (int t = 0; t < 4; t++) mma16816(acc[mi][t], af[mi], bf[t]);
        }

        // epilogue
        float cs[4][2];
#pragma unroll
        for (int t = 0; t < 4; t++) { cs[t][0] = 0.0f; cs[t][1] = 0.0f; }
#pragma unroll
        for (int mi = 0; mi < 2; mi++) {
            int r0 = wr * 32 + mi * 16 + (l >> 2);
            int r1 = r0 + 8;
            float m0 = ms[r0], m1 = ms[r1];
            float x20 = x2s[r0], x21 = x2s[r1];
            float o0 = 1.0f - x20, o1 = 1.0f - x21;
            bool v0ok = (tile0 + r0) < N, v1ok = (tile0 + r1) < N;
            float* p0r = out_node + (size_t)(tile0 + r0) * KC;
            float* p1r = out_node + (size_t)(tile0 + r1) * KC;
#pragma unroll
            for (int t = 0; t < 4; t++) {
                int col = wc * 32 + t * 8 + ((l & 3) << 1);
                float2 c2p = *(float2*)(c2s + col);
                float d0 = pdist(acc[mi][t][0], x20, o0, c2p.x) * m0;
                float d1 = pdist(acc[mi][t][1], x20, o0, c2p.y) * m0;
                float d2 = pdist(acc[mi][t][2], x21, o1, c2p.x) * m1;
                float d3 = pdist(acc[mi][t][3], x21, o1, c2p.y) * m1;
                if (v0ok) *(float2*)(p0r + col) = make_float2(d0, d1);
                if (v1ok) *(float2*)(p1r + col) = make_float2(d2, d3);
                cs[t][0] += d0 + d2;
                cs[t][1] += d1 + d3;
            }
        }
#pragma unroll
        for (int t = 0; t < 4; t++) {
#pragma unroll
            for (int o = 4; o <= 16; o <<= 1) {
                cs[t][0] += __shfl_xor_sync(0xffffffffu, cs[t][0], o);
                cs[t][1] += __shfl_xor_sync(0xffffffffu, cs[t][1], o);
            }
            if (l < 4) {
                int col = wc * 32 + t * 8 + ((l & 3) << 1);
                atomicAdd(&scol[col], cs[t][0]);
                atomicAdd(&scol[col + 1], cs[t][1]);
            }
        }
        __syncthreads();                       // protect A/ms/x2s before next convert
    }

    if (tid < KC) atomicAdd(&g_acc[tid], scol[tid]);
    if (tid == 0) atomicAdd(&g_masksum, *msum);
}

// ---- Kernel 3 ----
__global__ void finish_kernel(float* __restrict__ out_graph) {
    int k = threadIdx.x;
    if (k < KC) out_graph[k] = g_acc[k] / g_masksum;
}

extern "C" void kernel_launch(void* const* d_in, const int* in_sizes, int n_in,
                              void* d_out, int out_size) {
    const float* x    = (const float*)d_in[0];
    const float* mask = (const float*)d_in[1];
    const float* cw   = (const float*)d_in[2];
    const int N = in_sizes[1];
    float* out = (float*)d_out;

    cudaFuncSetAttribute(dist_kernel, cudaFuncAttributeMaxDynamicSharedMemorySize, SM_TOTAL);

    prep_kernel<<<32, 128>>>(cw);
    const int ntiles = (N + TM - 1) / TM;
    dist_kernel<<<148, TPB, SM_TOTAL>>>(x, mask, out + KC, N, ntiles);
    finish_kernel<<<1, KC>>>(out);
}